// round 1
// baseline (speedup 1.0000x reference)
#include <cuda_runtime.h>
#include <cstdint>

#define BATCH   16384
#define IN_DIM  2048
#define NTREES  10
#define NDEC    255
#define NLEAF_E 256                   // effective leaves (pairs are identical)
#define CLASSES 1000
#define KDIM2   (NTREES * NLEAF_E)    // 2560

// Scratch (allowed: __device__ globals, no allocation)
__device__ float g_leafpe[(size_t)KDIM2 * CLASSES];   // [2560][1000], includes /NTREES
__device__ float g_prob[(size_t)BATCH * KDIM2];       // [16384][2560]

// ---------------------------------------------------------------------------
// K1: leafp_eff[t][m][c] = (softmax(w_l[t][2m])[c] + softmax(w_l[t][2m+1])[c]) / 10
// grid = NTREES*256 blocks, 256 threads
// ---------------------------------------------------------------------------
__global__ __launch_bounds__(256) void k1_softmax(const float* __restrict__ wl) {
    const int blk = blockIdx.x;
    const int t   = blk >> 8;
    const int m   = blk & 255;
    const int tid = threadIdx.x;

    __shared__ float s[2][CLASSES];
    __shared__ float red[256];

    const float* r0 = wl + (size_t)(t * 512 + 2 * m) * CLASSES;
    for (int i = tid; i < CLASSES; i += 256) {
        s[0][i] = r0[i];
        s[1][i] = r0[CLASSES + i];
    }
    __syncthreads();

    float inv[2];
    for (int h = 0; h < 2; h++) {
        float mx = -1e30f;
        for (int i = tid; i < CLASSES; i += 256) mx = fmaxf(mx, s[h][i]);
        red[tid] = mx;
        __syncthreads();
        for (int o = 128; o > 0; o >>= 1) {
            if (tid < o) red[tid] = fmaxf(red[tid], red[tid + o]);
            __syncthreads();
        }
        const float M = red[0];
        __syncthreads();
        float sm = 0.f;
        for (int i = tid; i < CLASSES; i += 256) {
            float e = __expf(s[h][i] - M);
            s[h][i] = e;
            sm += e;
        }
        red[tid] = sm;
        __syncthreads();
        for (int o = 128; o > 0; o >>= 1) {
            if (tid < o) red[tid] += red[tid + o];
            __syncthreads();
        }
        inv[h] = 1.f / red[0];
        __syncthreads();
    }

    float* dst = g_leafpe + (size_t)(t * NLEAF_E + m) * CLASSES;
    const float sc = 1.f / (float)NTREES;
    for (int i = tid; i < CLASSES; i += 256)
        dst[i] = (s[0][i] * inv[0] + s[1][i] * inv[1]) * sc;
}

// ---------------------------------------------------------------------------
// K2: per (tree, 64-row batch tile):
//     logits 64x256 = x[64x2048] @ w_d[t][2048x255(pad 256)]
//     -> sigmoid -> 8-level path products -> g_prob[row][t*256+m]
// grid = (BATCH/64, NTREES), 256 threads, 8x8 microtile
// ---------------------------------------------------------------------------
__global__ __launch_bounds__(256) void k2_forest(const float* __restrict__ x,
                                                 const float* __restrict__ wd) {
    const int t    = blockIdx.y;
    const int row0 = blockIdx.x * 64;
    const int tid  = threadIdx.x;
    const int tr   = tid >> 5;    // 0..7 (warp id = thread-row)
    const int tc   = tid & 31;    // 0..31 (thread-col)

    // union: GEMM stage uses As(16x68)+Bs(16x256) = 20736B, epilogue uses P(32x256)=32768B
    __shared__ __align__(16) float smem[32 * 256];
    float (*As)[68]  = (float (*)[68])smem;
    float (*Bs)[256] = (float (*)[256])(smem + 16 * 68);
    float (*P)[256]  = (float (*)[256])smem;

    float acc[8][8];
#pragma unroll
    for (int i = 0; i < 8; i++)
#pragma unroll
        for (int j = 0; j < 8; j++) acc[i][j] = 0.f;

    const int lrow = tid >> 2;        // 0..63
    const int kk4  = (tid & 3) * 4;   // 0,4,8,12
    const float* xp = x + (size_t)(row0 + lrow) * IN_DIM + kk4;
    const float* wp = wd + (size_t)t * IN_DIM * NDEC;

    for (int k0 = 0; k0 < IN_DIM; k0 += 16) {
        float4 xa = *(const float4*)(xp + k0);
        As[kk4 + 0][lrow] = xa.x;
        As[kk4 + 1][lrow] = xa.y;
        As[kk4 + 2][lrow] = xa.z;
        As[kk4 + 3][lrow] = xa.w;
#pragma unroll
        for (int i = 0; i < 16; i++)
            Bs[i][tid] = (tid < NDEC) ? wp[(size_t)(k0 + i) * NDEC + tid] : 0.f;
        __syncthreads();
#pragma unroll
        for (int kk = 0; kk < 16; kk++) {
            float4 a0 = *(const float4*)&As[kk][tr * 8];
            float4 a1 = *(const float4*)&As[kk][tr * 8 + 4];
            float4 b0 = *(const float4*)&Bs[kk][tc * 8];
            float4 b1 = *(const float4*)&Bs[kk][tc * 8 + 4];
            float av[8] = {a0.x, a0.y, a0.z, a0.w, a1.x, a1.y, a1.z, a1.w};
            float bv[8] = {b0.x, b0.y, b0.z, b0.w, b1.x, b1.y, b1.z, b1.w};
#pragma unroll
            for (int i = 0; i < 8; i++)
#pragma unroll
                for (int j = 0; j < 8; j++)
                    acc[i][j] = fmaf(av[i], bv[j], acc[i][j]);
        }
        __syncthreads();
    }

    // Epilogue in two 32-row waves so P[32][256] can alias As/Bs.
    for (int wave = 0; wave < 2; wave++) {
        __syncthreads();
        if ((tr >> 2) == wave) {
            const int rl = (tr & 3) * 8;
#pragma unroll
            for (int i = 0; i < 8; i++)
#pragma unroll
                for (int j = 0; j < 8; j++) {
                    float z = acc[i][j];
                    P[rl + i][tc * 8 + j] = 1.f / (1.f + __expf(-z));
                }
        }
        __syncthreads();
        // products: rows [wave*32, wave*32+32), all 256 effective leaves
        for (int it = 0; it < 32; it++) {
            const int r = it;
            const int m = tid;
            float prod = 1.f;
#pragma unroll
            for (int n = 0; n < 8; n++) {
                int prefix = m >> (8 - n);
                int node   = (1 << n) - 1 + prefix;
                float p    = P[r][node];
                prod *= ((m >> (7 - n)) & 1) ? (1.f - p) : p;
            }
            g_prob[(size_t)(row0 + wave * 32 + r) * KDIM2 + t * NLEAF_E + m] = prod;
        }
    }
}

// ---------------------------------------------------------------------------
// K3: out[64x(<=256)] = g_prob[64x2560] @ g_leafpe[2560x1000]
// grid = (BATCH/64, 4), 256 threads, 8x8 microtile
// ---------------------------------------------------------------------------
__global__ __launch_bounds__(256) void k3_out(float* __restrict__ out) {
    const int ct   = blockIdx.y;        // column tile 0..3 (cols ct*256..)
    const int row0 = blockIdx.x * 64;
    const int tid  = threadIdx.x;
    const int tr   = tid >> 5;
    const int tc   = tid & 31;

    __shared__ __align__(16) float As[16][68];
    __shared__ __align__(16) float Bs[16][256];

    float acc[8][8];
#pragma unroll
    for (int i = 0; i < 8; i++)
#pragma unroll
        for (int j = 0; j < 8; j++) acc[i][j] = 0.f;

    const int lrow = tid >> 2;
    const int kk4  = (tid & 3) * 4;
    const float* ap = g_prob + (size_t)(row0 + lrow) * KDIM2 + kk4;
    const int gc = ct * 256 + tid;

    for (int k0 = 0; k0 < KDIM2; k0 += 16) {
        float4 xa = *(const float4*)(ap + k0);
        As[kk4 + 0][lrow] = xa.x;
        As[kk4 + 1][lrow] = xa.y;
        As[kk4 + 2][lrow] = xa.z;
        As[kk4 + 3][lrow] = xa.w;
#pragma unroll
        for (int i = 0; i < 16; i++)
            Bs[i][tid] = (gc < CLASSES) ? g_leafpe[(size_t)(k0 + i) * CLASSES + gc] : 0.f;
        __syncthreads();
#pragma unroll
        for (int kk = 0; kk < 16; kk++) {
            float4 a0 = *(const float4*)&As[kk][tr * 8];
            float4 a1 = *(const float4*)&As[kk][tr * 8 + 4];
            float4 b0 = *(const float4*)&Bs[kk][tc * 8];
            float4 b1 = *(const float4*)&Bs[kk][tc * 8 + 4];
            float av[8] = {a0.x, a0.y, a0.z, a0.w, a1.x, a1.y, a1.z, a1.w};
            float bv[8] = {b0.x, b0.y, b0.z, b0.w, b1.x, b1.y, b1.z, b1.w};
#pragma unroll
            for (int i = 0; i < 8; i++)
#pragma unroll
                for (int j = 0; j < 8; j++)
                    acc[i][j] = fmaf(av[i], bv[j], acc[i][j]);
        }
        __syncthreads();
    }

#pragma unroll
    for (int i = 0; i < 8; i++) {
        const int row = row0 + tr * 8 + i;
#pragma unroll
        for (int j = 0; j < 8; j++) {
            const int c = ct * 256 + tc * 8 + j;
            if (c < CLASSES) out[(size_t)row * CLASSES + c] = acc[i][j];
        }
    }
}

// ---------------------------------------------------------------------------
extern "C" void kernel_launch(void* const* d_in, const int* in_sizes, int n_in,
                              void* d_out, int out_size) {
    const float* x  = nullptr;
    const float* wd = nullptr;
    const float* wl = nullptr;
    for (int i = 0; i < n_in; i++) {
        if (in_sizes[i] == BATCH * IN_DIM)               x  = (const float*)d_in[i];
        else if (in_sizes[i] == NTREES * IN_DIM * NDEC)  wd = (const float*)d_in[i];
        else if (in_sizes[i] == NTREES * 512 * CLASSES)  wl = (const float*)d_in[i];
    }
    float* out = (float*)d_out;

    k1_softmax<<<NTREES * NLEAF_E, 256>>>(wl);
    k2_forest<<<dim3(BATCH / 64, NTREES), 256>>>(x, wd);
    k3_out<<<dim3(BATCH / 64, 4), 256>>>(out);
}

// round 3
// speedup vs baseline: 2.7099x; 2.7099x over previous
#include <cuda_runtime.h>
#include <cuda_bf16.h>
#include <cstdint>

#define BATCH   16384
#define IN_DIM  2048
#define NTREES  10
#define NDEC    255
#define CLASSES 1000
#define KDIM2   2560          // NTREES * 256
#define NPAD    1024          // padded class rows for K3 B matrix

// ---------------- device scratch (zero-initialized at module load) ----------
__device__ __nv_bfloat16 g_xh[(size_t)BATCH * IN_DIM];
__device__ __nv_bfloat16 g_xl[(size_t)BATCH * IN_DIM];
__device__ __nv_bfloat16 g_wh[(size_t)NTREES * 256 * IN_DIM];   // [t][n][k] K-major
__device__ __nv_bfloat16 g_wlo[(size_t)NTREES * 256 * IN_DIM];
__device__ __nv_bfloat16 g_lpb[(size_t)NPAD * KDIM2];           // [class][k] K-major
__device__ float         g_dec[(size_t)BATCH * KDIM2];          // logits fp32
__device__ __nv_bfloat16 g_prob[(size_t)BATCH * KDIM2];

// ---------------- PTX helpers ----------------------------------------------
__device__ __forceinline__ uint32_t smem_u32(const void* p) {
    uint32_t a;
    asm("{ .reg .u64 t; cvta.to.shared.u64 t, %1; cvt.u32.u64 %0, t; }" : "=r"(a) : "l"(p));
    return a;
}
#define CPA(dst, src) asm volatile("cp.async.cg.shared.global [%0], [%1], 16;" :: "r"(dst), "l"(src))
#define CPC()  asm volatile("cp.async.commit_group;" ::: "memory")
#define CPW0() asm volatile("cp.async.wait_group 0;" ::: "memory")

__device__ __forceinline__ void ldsm4(uint32_t* r, uint32_t addr) {
    asm volatile("ldmatrix.sync.aligned.m8n8.x4.shared.b16 {%0,%1,%2,%3}, [%4];"
                 : "=r"(r[0]), "=r"(r[1]), "=r"(r[2]), "=r"(r[3]) : "r"(addr));
}
__device__ __forceinline__ void mma16816(float* c, const uint32_t* a, const uint32_t* b) {
    asm volatile("mma.sync.aligned.m16n8k16.row.col.f32.bf16.bf16.f32 "
                 "{%0,%1,%2,%3}, {%4,%5,%6,%7}, {%8,%9}, {%0,%1,%2,%3};"
                 : "+f"(c[0]), "+f"(c[1]), "+f"(c[2]), "+f"(c[3])
                 : "r"(a[0]), "r"(a[1]), "r"(a[2]), "r"(a[3]), "r"(b[0]), "r"(b[1]));
}

// ---------------------------------------------------------------------------
// P1: x -> (xh, xl) bf16
// ---------------------------------------------------------------------------
__global__ __launch_bounds__(256) void p1_xconv(const float* __restrict__ x) {
    size_t i = (size_t)blockIdx.x * 256 + threadIdx.x;     // float4 index
    float4 v = ((const float4*)x)[i];
    __nv_bfloat16 h0 = __float2bfloat16(v.x), h1 = __float2bfloat16(v.y);
    __nv_bfloat16 h2 = __float2bfloat16(v.z), h3 = __float2bfloat16(v.w);
    __nv_bfloat16 l0 = __float2bfloat16(v.x - __bfloat162float(h0));
    __nv_bfloat16 l1 = __float2bfloat16(v.y - __bfloat162float(h1));
    __nv_bfloat16 l2 = __float2bfloat16(v.z - __bfloat162float(h2));
    __nv_bfloat16 l3 = __float2bfloat16(v.w - __bfloat162float(h3));
    __nv_bfloat162 ph0{h0, h1}, ph1{h2, h3}, pl0{l0, l1}, pl1{l2, l3};
    uint2 uh{*(uint32_t*)&ph0, *(uint32_t*)&ph1};
    uint2 ul{*(uint32_t*)&pl0, *(uint32_t*)&pl1};
    ((uint2*)g_xh)[i] = uh;
    ((uint2*)g_xl)[i] = ul;
}

// ---------------------------------------------------------------------------
// P2: w_d [t][k][255] -> g_wh/g_wlo [t][n(256 pad)][k] bf16 K-major
// ---------------------------------------------------------------------------
__global__ __launch_bounds__(256) void p2_wconv(const float* __restrict__ wd) {
    __shared__ __nv_bfloat16 sh[64][258];
    __shared__ __nv_bfloat16 sl[64][258];
    const int t = blockIdx.y, k0 = blockIdx.x * 64;
    const int n = threadIdx.x;
    const float* wp = wd + (size_t)t * IN_DIM * NDEC;
    for (int kk = 0; kk < 64; kk++) {
        float v = (n < NDEC) ? wp[(size_t)(k0 + kk) * NDEC + n] : 0.f;
        __nv_bfloat16 h = __float2bfloat16(v);
        sh[kk][n] = h;
        sl[kk][n] = __float2bfloat16(v - __bfloat162float(h));
    }
    __syncthreads();
#pragma unroll
    for (int i = 0; i < 8; i++) {
        int u = threadIdx.x + i * 256;
        int nn = u >> 3, ch = u & 7;
        uint32_t wh[4], wl[4];
#pragma unroll
        for (int j = 0; j < 4; j++) {
            __nv_bfloat162 ph{sh[ch * 8 + 2 * j][nn], sh[ch * 8 + 2 * j + 1][nn]};
            __nv_bfloat162 pl{sl[ch * 8 + 2 * j][nn], sl[ch * 8 + 2 * j + 1][nn]};
            wh[j] = *(uint32_t*)&ph;
            wl[j] = *(uint32_t*)&pl;
        }
        size_t off = (((size_t)t << 8) + nn) * IN_DIM + k0 + ch * 8;
        *(uint4*)(g_wh + off)  = make_uint4(wh[0], wh[1], wh[2], wh[3]);
        *(uint4*)(g_wlo + off) = make_uint4(wl[0], wl[1], wl[2], wl[3]);
    }
}

// ---------------------------------------------------------------------------
// K1: paired softmax of w_l -> g_lpb [class][t*256+m] bf16 (K-major for K3)
// ---------------------------------------------------------------------------
__global__ __launch_bounds__(256) void k1_softmax(const float* __restrict__ wl) {
    const int blk = blockIdx.x;
    const int t = blk >> 8, m = blk & 255;
    const int tid = threadIdx.x;
    __shared__ float s[2][CLASSES];
    __shared__ float red[256];

    const float* r0 = wl + (size_t)(t * 512 + 2 * m) * CLASSES;
    for (int i = tid; i < CLASSES; i += 256) { s[0][i] = r0[i]; s[1][i] = r0[CLASSES + i]; }
    __syncthreads();

    float inv[2];
    for (int h = 0; h < 2; h++) {
        float mx = -1e30f;
        for (int i = tid; i < CLASSES; i += 256) mx = fmaxf(mx, s[h][i]);
        red[tid] = mx; __syncthreads();
        for (int o = 128; o > 0; o >>= 1) { if (tid < o) red[tid] = fmaxf(red[tid], red[tid + o]); __syncthreads(); }
        const float M = red[0]; __syncthreads();
        float sm = 0.f;
        for (int i = tid; i < CLASSES; i += 256) { float e = __expf(s[h][i] - M); s[h][i] = e; sm += e; }
        red[tid] = sm; __syncthreads();
        for (int o = 128; o > 0; o >>= 1) { if (tid < o) red[tid] += red[tid + o]; __syncthreads(); }
        inv[h] = 1.f / red[0]; __syncthreads();
    }
    const float sc = 1.f / (float)NTREES;
    for (int i = tid; i < CLASSES; i += 256)
        g_lpb[(size_t)i * KDIM2 + t * 256 + m] =
            __float2bfloat16((s[0][i] * inv[0] + s[1][i] * inv[1]) * sc);
}

// ---------------------------------------------------------------------------
// K2: mma.sync split-bf16 GEMM  C[128x128] = x[128x2048] * w^T
//     3 terms: xh*wh + xh*wl + xl*wh.  Writes logits fp32 to g_dec.
// grid (20, BATCH/128)  [x-fast so 20 trees/ct share A rows in a wave]
// dyn smem 81920: 2 stages x {Ah,Al,Bh,Bl}[128][40] bf16
// ---------------------------------------------------------------------------
#define ST2  40960
#define MOFF 10240
__global__ __launch_bounds__(256, 1) void k2_mma() {
    extern __shared__ char smem[];
    const uint32_t sb = smem_u32(smem);
    const int t    = blockIdx.x >> 1;
    const int ct   = blockIdx.x & 1;
    const int row0 = blockIdx.y * 128;
    const int tid  = threadIdx.x;
    const int lane = tid & 31, wid = tid >> 5;
    const int wm = wid & 3, wn = wid >> 2;

    // cp.async mapping
    const int lrow = tid >> 2;         // rows 0..63 (+64 on second pass)
    const int lkc  = tid & 3;          // 16B chunk within 32-k row
    const __nv_bfloat16* pA  = g_xh  + (size_t)row0 * IN_DIM;
    const __nv_bfloat16* pAl = g_xl  + (size_t)row0 * IN_DIM;
    const __nv_bfloat16* pB  = g_wh  + ((size_t)t * 256 + ct * 128) * IN_DIM;
    const __nv_bfloat16* pBl = g_wlo + ((size_t)t * 256 + ct * 128) * IN_DIM;

    // ldmatrix per-lane offsets (bytes, within a matrix)
    const int arow = lane & 15, akof = (lane >> 4) * 8;
    const uint32_t aoff0 = ((wm * 32 + arow) * 40 + akof) * 2;
    const uint32_t aoff1 = ((wm * 32 + 16 + arow) * 40 + akof) * 2;
    const int bg = lane >> 3;
    const int brow = ((bg >> 1) * 8) + (lane & 7);
    const int bkof = (bg & 1) * 8;
    uint32_t boff[4];
#pragma unroll
    for (int q = 0; q < 4; q++)
        boff[q] = ((wn * 64 + q * 16 + brow) * 40 + bkof) * 2;

    float acc[2][8][4];
#pragma unroll
    for (int a = 0; a < 2; a++)
#pragma unroll
        for (int b = 0; b < 8; b++)
#pragma unroll
            for (int c = 0; c < 4; c++) acc[a][b][c] = 0.f;

    const int NC = IN_DIM / 32;

    // prologue: load chunk 0 into stage 0
    {
        const uint32_t st = sb;
#pragma unroll
        for (int i = 0; i < 2; i++) {
            int r = lrow + i * 64;
            uint32_t d = st + (r * 40 + lkc * 8) * 2;
            size_t so = (size_t)r * IN_DIM + lkc * 8;
            CPA(d,            (const char*)(pA  + so));
            CPA(d + MOFF,     (const char*)(pAl + so));
            CPA(d + 2 * MOFF, (const char*)(pB  + so));
            CPA(d + 3 * MOFF, (const char*)(pBl + so));
        }
        CPC();
    }

    for (int c = 0; c < NC; c++) {
        CPW0();
        __syncthreads();
        if (c + 1 < NC) {
            const uint32_t st = sb + ((c + 1) & 1) * ST2;
            const size_t k0 = (size_t)(c + 1) * 32;
#pragma unroll
            for (int i = 0; i < 2; i++) {
                int r = lrow + i * 64;
                uint32_t d = st + (r * 40 + lkc * 8) * 2;
                size_t so = (size_t)r * IN_DIM + k0 + lkc * 8;
                CPA(d,            (const char*)(pA  + so));
                CPA(d + MOFF,     (const char*)(pAl + so));
                CPA(d + 2 * MOFF, (const char*)(pB  + so));
                CPA(d + 3 * MOFF, (const char*)(pBl + so));
            }
            CPC();
        }
        const uint32_t st = sb + (c & 1) * ST2;
#pragma unroll
        for (int ks = 0; ks < 2; ks++) {
            const uint32_t kb = ks * 32;   // 16 bf16 = 32B
            uint32_t ah[2][4], al[2][4];
            ldsm4(ah[0], st + aoff0 + kb);
            ldsm4(ah[1], st + aoff1 + kb);
            ldsm4(al[0], st + MOFF + aoff0 + kb);
            ldsm4(al[1], st + MOFF + aoff1 + kb);
            uint32_t bh[4][4], bl[4][4];
#pragma unroll
            for (int q = 0; q < 4; q++) {
                ldsm4(bh[q], st + 2 * MOFF + boff[q] + kb);
                ldsm4(bl[q], st + 3 * MOFF + boff[q] + kb);
            }
#pragma unroll
            for (int mt = 0; mt < 2; mt++)
#pragma unroll
                for (int q = 0; q < 4; q++) {
                    mma16816(acc[mt][2 * q],     ah[mt], &bh[q][0]);
                    mma16816(acc[mt][2 * q + 1], ah[mt], &bh[q][2]);
                    mma16816(acc[mt][2 * q],     ah[mt], &bl[q][0]);
                    mma16816(acc[mt][2 * q + 1], ah[mt], &bl[q][2]);
                    mma16816(acc[mt][2 * q],     al[mt], &bh[q][0]);
                    mma16816(acc[mt][2 * q + 1], al[mt], &bh[q][2]);
                }
        }
    }

    // write logits fp32
    const int cbase = t * 256 + ct * 128 + wn * 64 + 2 * (lane & 3);
    const int rbase = row0 + wm * 32 + (lane >> 2);
#pragma unroll
    for (int mt = 0; mt < 2; mt++)
#pragma unroll
        for (int j = 0; j < 8; j++) {
            int col = cbase + j * 8;
            int row = rbase + mt * 16;
            *(float2*)(g_dec + (size_t)row * KDIM2 + col) = make_float2(acc[mt][j][0], acc[mt][j][1]);
            *(float2*)(g_dec + (size_t)(row + 8) * KDIM2 + col) = make_float2(acc[mt][j][2], acc[mt][j][3]);
        }
}

// ---------------------------------------------------------------------------
// K2b: sigmoid + tree path products.  block = one batch row (2560 logits)
// ---------------------------------------------------------------------------
__global__ __launch_bounds__(256) void k2b_prod() {
    const int b   = blockIdx.x;
    const int tid = threadIdx.x;
    __shared__ float s[KDIM2];
    const float* src = g_dec + (size_t)b * KDIM2;
#pragma unroll
    for (int i = 0; i < 10; i++) {
        float z = src[i * 256 + tid];
        s[i * 256 + tid] = 1.f / (1.f + __expf(-z));
    }
    __syncthreads();
    __nv_bfloat16* dst = g_prob + (size_t)b * KDIM2;
    const int m = tid;
#pragma unroll
    for (int t = 0; t < 10; t++) {
        float prod = 1.f;
#pragma unroll
        for (int n = 0; n < 8; n++) {
            int node = (1 << n) - 1 + (m >> (8 - n));
            float p = s[t * 256 + node];
            prod *= ((m >> (7 - n)) & 1) ? (1.f - p) : p;
        }
        dst[t * 256 + m] = __float2bfloat16(prod);
    }
}

// ---------------------------------------------------------------------------
// K3: mma.sync bf16 GEMM  out[128x128] = prob[128x2560] * leafp^T
// grid (8, BATCH/128), dyn smem 40960: 2 stages x {A,B}[128][40]
// ---------------------------------------------------------------------------
__global__ __launch_bounds__(256, 1) void k3_mma(float* __restrict__ out) {
    extern __shared__ char smem[];
    const uint32_t sb = smem_u32(smem);
    const int ct   = blockIdx.x;
    const int row0 = blockIdx.y * 128;
    const int tid  = threadIdx.x;
    const int lane = tid & 31, wid = tid >> 5;
    const int wm = wid & 3, wn = wid >> 2;

    const int lrow = tid >> 2, lkc = tid & 3;
    const __nv_bfloat16* pA = g_prob + (size_t)row0 * KDIM2;
    const __nv_bfloat16* pB = g_lpb + (size_t)(ct * 128) * KDIM2;

    const int arow = lane & 15, akof = (lane >> 4) * 8;
    const uint32_t aoff0 = ((wm * 32 + arow) * 40 + akof) * 2;
    const uint32_t aoff1 = ((wm * 32 + 16 + arow) * 40 + akof) * 2;
    const int bg = lane >> 3;
    const int brow = ((bg >> 1) * 8) + (lane & 7);
    const int bkof = (bg & 1) * 8;
    uint32_t boff[4];
#pragma unroll
    for (int q = 0; q < 4; q++)
        boff[q] = ((wn * 64 + q * 16 + brow) * 40 + bkof) * 2;

    float acc[2][8][4];
#pragma unroll
    for (int a = 0; a < 2; a++)
#pragma unroll
        for (int b = 0; b < 8; b++)
#pragma unroll
            for (int c = 0; c < 4; c++) acc[a][b][c] = 0.f;

    const int NC = KDIM2 / 32;   // 80

    {
        const uint32_t st = sb;
#pragma unroll
        for (int i = 0; i < 2; i++) {
            int r = lrow + i * 64;
            uint32_t d = st + (r * 40 + lkc * 8) * 2;
            size_t so = (size_t)r * KDIM2 + lkc * 8;
            CPA(d,        (const char*)(pA + so));
            CPA(d + MOFF, (const char*)(pB + so));
        }
        CPC();
    }

    for (int c = 0; c < NC; c++) {
        CPW0();
        __syncthreads();
        if (c + 1 < NC) {
            const uint32_t st = sb + ((c + 1) & 1) * (2 * MOFF);
            const size_t k0 = (size_t)(c + 1) * 32;
#pragma unroll
            for (int i = 0; i < 2; i++) {
                int r = lrow + i * 64;
                uint32_t d = st + (r * 40 + lkc * 8) * 2;
                size_t so = (size_t)r * KDIM2 + k0 + lkc * 8;
                CPA(d,        (const char*)(pA + so));
                CPA(d + MOFF, (const char*)(pB + so));
            }
            CPC();
        }
        const uint32_t st = sb + (c & 1) * (2 * MOFF);
#pragma unroll
        for (int ks = 0; ks < 2; ks++) {
            const uint32_t kb = ks * 32;
            uint32_t a[2][4];
            ldsm4(a[0], st + aoff0 + kb);
            ldsm4(a[1], st + aoff1 + kb);
            uint32_t b[4][4];
#pragma unroll
            for (int q = 0; q < 4; q++)
                ldsm4(b[q], st + MOFF + boff[q] + kb);
#pragma unroll
            for (int mt = 0; mt < 2; mt++)
#pragma unroll
                for (int q = 0; q < 4; q++) {
                    mma16816(acc[mt][2 * q],     a[mt], &b[q][0]);
                    mma16816(acc[mt][2 * q + 1], a[mt], &b[q][2]);
                }
        }
    }

    const int cbase = ct * 128 + wn * 64 + 2 * (lane & 3);
    const int rbase = row0 + wm * 32 + (lane >> 2);
#pragma unroll
    for (int mt = 0; mt < 2; mt++)
#pragma unroll
        for (int j = 0; j < 8; j++) {
            int col = cbase + j * 8;
            int r0w = rbase + mt * 16;
            if (col + 1 < CLASSES) {
                *(float2*)(out + (size_t)r0w * CLASSES + col) = make_float2(acc[mt][j][0], acc[mt][j][1]);
                *(float2*)(out + (size_t)(r0w + 8) * CLASSES + col) = make_float2(acc[mt][j][2], acc[mt][j][3]);
            } else if (col < CLASSES) {
                out[(size_t)r0w * CLASSES + col] = acc[mt][j][0];
                out[(size_t)(r0w + 8) * CLASSES + col] = acc[mt][j][2];
            }
        }
}

// ---------------------------------------------------------------------------
extern "C" void kernel_launch(void* const* d_in, const int* in_sizes, int n_in,
                              void* d_out, int out_size) {
    const float* x = nullptr;
    const float* wd = nullptr;
    const float* wl = nullptr;
    for (int i = 0; i < n_in; i++) {
        if (in_sizes[i] == BATCH * IN_DIM)              x = (const float*)d_in[i];
        else if (in_sizes[i] == NTREES * IN_DIM * NDEC) wd = (const float*)d_in[i];
        else if (in_sizes[i] == NTREES * 512 * CLASSES) wl = (const float*)d_in[i];
    }
    float* out = (float*)d_out;

    cudaFuncSetAttribute(k2_mma, cudaFuncAttributeMaxDynamicSharedMemorySize, 2 * ST2);
    cudaFuncSetAttribute(k3_mma, cudaFuncAttributeMaxDynamicSharedMemorySize, 4 * MOFF);

    p1_xconv<<<(BATCH * IN_DIM / 4) / 256, 256>>>(x);
    p2_wconv<<<dim3(IN_DIM / 64, NTREES), 256>>>(wd);
    k1_softmax<<<NTREES * 256, 256>>>(wl);
    k2_mma<<<dim3(NTREES * 2, BATCH / 128), 256, 2 * ST2>>>();
    k2b_prod<<<BATCH, 256>>>();
    k3_mma<<<dim3(8, BATCH / 128), 256, 4 * MOFF>>>(out);
}

// round 4
// speedup vs baseline: 3.5580x; 1.3129x over previous
#include <cuda_runtime.h>
#include <cuda_bf16.h>
#include <cstdint>

#define BATCH   16384
#define IN_DIM  2048
#define NTREES  10
#define NDEC    255
#define CLASSES 1000
#define KDIM2   2560          // NTREES * 256
#define NPAD    1024          // padded class rows for K3 B matrix

// ---------------- device scratch ----------------
__device__ float         g_wt[(size_t)NTREES * 256 * IN_DIM];   // tf32-rounded, [t][n][k]
__device__ __nv_bfloat16 g_lpb[(size_t)NPAD * KDIM2];           // [class][k] K-major
__device__ float         g_dec[(size_t)BATCH * KDIM2];          // logits fp32
__device__ __nv_bfloat16 g_prob[(size_t)BATCH * KDIM2];

// ---------------- PTX helpers ----------------
__device__ __forceinline__ uint32_t smem_u32(const void* p) {
    uint32_t a;
    asm("{ .reg .u64 t; cvta.to.shared.u64 t, %1; cvt.u32.u64 %0, t; }" : "=r"(a) : "l"(p));
    return a;
}
#define CPA(dst, src) asm volatile("cp.async.cg.shared.global [%0], [%1], 16;" :: "r"(dst), "l"(src))
#define CPC()  asm volatile("cp.async.commit_group;" ::: "memory")
#define CPW1() asm volatile("cp.async.wait_group 1;" ::: "memory")

__device__ __forceinline__ void ldsm4(uint32_t* r, uint32_t addr) {
    asm volatile("ldmatrix.sync.aligned.m8n8.x4.shared.b16 {%0,%1,%2,%3}, [%4];"
                 : "=r"(r[0]), "=r"(r[1]), "=r"(r[2]), "=r"(r[3]) : "r"(addr));
}
__device__ __forceinline__ void mma16816(float* c, const uint32_t* a, const uint32_t* b) {
    asm volatile("mma.sync.aligned.m16n8k16.row.col.f32.bf16.bf16.f32 "
                 "{%0,%1,%2,%3}, {%4,%5,%6,%7}, {%8,%9}, {%0,%1,%2,%3};"
                 : "+f"(c[0]), "+f"(c[1]), "+f"(c[2]), "+f"(c[3])
                 : "r"(a[0]), "r"(a[1]), "r"(a[2]), "r"(a[3]), "r"(b[0]), "r"(b[1]));
}
__device__ __forceinline__ void mma1688(float* c, const uint32_t* a, const uint32_t* b) {
    asm volatile("mma.sync.aligned.m16n8k8.row.col.f32.tf32.tf32.f32 "
                 "{%0,%1,%2,%3}, {%4,%5,%6,%7}, {%8,%9}, {%0,%1,%2,%3};"
                 : "+f"(c[0]), "+f"(c[1]), "+f"(c[2]), "+f"(c[3])
                 : "r"(a[0]), "r"(a[1]), "r"(a[2]), "r"(a[3]), "r"(b[0]), "r"(b[1]));
}
__device__ __forceinline__ float cvt_tf32(float v) {
    uint32_t r;
    asm("cvt.rna.tf32.f32 %0, %1;" : "=r"(r) : "f"(v));
    return __uint_as_float(r);
}

// ---------------------------------------------------------------------------
// P2: w_d [t][k][255] -> g_wt [t][n(256 pad)][k] fp32 (tf32-rounded), K-major
// grid (64, 10), 256 threads
// ---------------------------------------------------------------------------
__global__ __launch_bounds__(256) void p2_wconv(const float* __restrict__ wd) {
    __shared__ float sh[32][257];
    const int t = blockIdx.y, k0 = blockIdx.x * 32;
    const int n = threadIdx.x;
    const float* wp = wd + (size_t)t * IN_DIM * NDEC;
#pragma unroll
    for (int kk = 0; kk < 32; kk++) {
        float v = (n < NDEC) ? wp[(size_t)(k0 + kk) * NDEC + n] : 0.f;
        sh[kk][n] = cvt_tf32(v);
    }
    __syncthreads();
    float* dst = g_wt + ((size_t)t * 256 + n) * IN_DIM + k0;
#pragma unroll
    for (int u = 0; u < 8; u++) {
        float4 v4;
        v4.x = sh[4 * u + 0][n];
        v4.y = sh[4 * u + 1][n];
        v4.z = sh[4 * u + 2][n];
        v4.w = sh[4 * u + 3][n];
        *(float4*)(dst + 4 * u) = v4;
    }
}

// ---------------------------------------------------------------------------
// K1: paired softmax of w_l -> g_lpb [class][t*256+m] bf16 (K-major for K3)
// ---------------------------------------------------------------------------
__global__ __launch_bounds__(256) void k1_softmax(const float* __restrict__ wl) {
    const int blk = blockIdx.x;
    const int t = blk >> 8, m = blk & 255;
    const int tid = threadIdx.x;
    __shared__ float s[2][CLASSES];
    __shared__ float red[256];

    const float* r0 = wl + (size_t)(t * 512 + 2 * m) * CLASSES;
    for (int i = tid; i < CLASSES; i += 256) { s[0][i] = r0[i]; s[1][i] = r0[CLASSES + i]; }
    __syncthreads();

    float inv[2];
    for (int h = 0; h < 2; h++) {
        float mx = -1e30f;
        for (int i = tid; i < CLASSES; i += 256) mx = fmaxf(mx, s[h][i]);
        red[tid] = mx; __syncthreads();
        for (int o = 128; o > 0; o >>= 1) { if (tid < o) red[tid] = fmaxf(red[tid], red[tid + o]); __syncthreads(); }
        const float M = red[0]; __syncthreads();
        float sm = 0.f;
        for (int i = tid; i < CLASSES; i += 256) { float e = __expf(s[h][i] - M); s[h][i] = e; sm += e; }
        red[tid] = sm; __syncthreads();
        for (int o = 128; o > 0; o >>= 1) { if (tid < o) red[tid] += red[tid + o]; __syncthreads(); }
        inv[h] = 1.f / red[0]; __syncthreads();
    }
    const float sc = 1.f / (float)NTREES;
    for (int i = tid; i < CLASSES; i += 256)
        g_lpb[(size_t)i * KDIM2 + t * 256 + m] =
            __float2bfloat16((s[0][i] * inv[0] + s[1][i] * inv[1]) * sc);
}

// ---------------------------------------------------------------------------
// K2: tf32 mma GEMM  C[128x128] = x[128x2048] * w^T, logits fp32 -> g_dec
// grid (20, BATCH/128), 256 threads, 3-stage cp.async pipeline
// smem: 3 x (A[128][36] + B[128][36]) fp32 = 110592 B
// ---------------------------------------------------------------------------
#define K2_ASZ 18432
#define K2_STG 36864
__global__ __launch_bounds__(256, 1) void k2_mma(const float* __restrict__ x) {
    extern __shared__ char smem[];
    const uint32_t sb = smem_u32(smem);
    const int t    = blockIdx.x >> 1;
    const int ct   = blockIdx.x & 1;
    const int row0 = blockIdx.y * 128;
    const int tid  = threadIdx.x;
    const int lane = tid & 31, wid = tid >> 5;
    const int wm = wid & 3, wn = wid >> 2;

    const float* pA = x + (size_t)row0 * IN_DIM;
    const float* pB = g_wt + ((size_t)t * 256 + ct * 128) * IN_DIM;

    // ldmatrix per-lane byte offsets (within a stage's A or B region)
    const int m_off = ((lane >> 3) & 1) * 8 + (lane & 7);
    const int ak    = (lane >> 4) * 4;
    const uint32_t aoff0 = ((wm * 32 + m_off) * 36 + ak) * 4;
    const uint32_t aoff1 = ((wm * 32 + 16 + m_off) * 36 + ak) * 4;
    const int n_off = (lane >> 4) * 8 + (lane & 7);
    const int bk    = ((lane >> 3) & 1) * 4;
    uint32_t boff[4];
#pragma unroll
    for (int q = 0; q < 4; q++)
        boff[q] = ((wn * 64 + q * 16 + n_off) * 36 + bk) * 4;

    float acc[2][8][4];
#pragma unroll
    for (int a = 0; a < 2; a++)
#pragma unroll
        for (int b = 0; b < 8; b++)
#pragma unroll
            for (int c = 0; c < 4; c++) acc[a][b][c] = 0.f;

    const int NC = IN_DIM / 32;   // 64 chunks of k=32

    // loader: chunk c into stage stg
#define K2_LOAD(cc, stg) do {                                                     \
        const uint32_t st_ = sb + (uint32_t)(stg) * K2_STG;                       \
        const int k0_ = (cc) * 32;                                                \
        _Pragma("unroll")                                                         \
        for (int i_ = 0; i_ < 4; i_++) {                                          \
            int idx_ = tid + i_ * 256;                                            \
            int row_ = idx_ >> 3, ch_ = idx_ & 7;                                 \
            uint32_t d_ = st_ + (row_ * 36 + ch_ * 4) * 4;                        \
            CPA(d_,          (const char*)(pA + (size_t)row_ * IN_DIM + k0_ + ch_ * 4)); \
            CPA(d_ + K2_ASZ, (const char*)(pB + (size_t)row_ * IN_DIM + k0_ + ch_ * 4)); \
        }                                                                         \
    } while (0)

    K2_LOAD(0, 0); CPC();
    K2_LOAD(1, 1); CPC();

    int stg = 0;
    for (int c = 0; c < NC; c++) {
        CPW1();
        __syncthreads();
        if (c + 2 < NC) {
            int ps = stg + 2; if (ps >= 3) ps -= 3;
            K2_LOAD(c + 2, ps);
        }
        CPC();
        const uint32_t st = sb + (uint32_t)stg * K2_STG;
#pragma unroll
        for (int ks = 0; ks < 4; ks++) {
            const uint32_t kb = ks * 32;      // 8 floats
            uint32_t a[2][4];
            ldsm4(a[0], st + aoff0 + kb);
            ldsm4(a[1], st + aoff1 + kb);
#pragma unroll
            for (int q = 0; q < 4; q++) {
                uint32_t b[4];
                ldsm4(b, st + K2_ASZ + boff[q] + kb);
                mma1688(acc[0][2 * q],     a[0], b + 0);
                mma1688(acc[0][2 * q + 1], a[0], b + 2);
                mma1688(acc[1][2 * q],     a[1], b + 0);
                mma1688(acc[1][2 * q + 1], a[1], b + 2);
            }
        }
        __syncthreads();
        stg++; if (stg == 3) stg = 0;
    }

    // write logits fp32
    const int cbase = t * 256 + ct * 128 + wn * 64 + 2 * (lane & 3);
    const int rbase = row0 + wm * 32 + (lane >> 2);
#pragma unroll
    for (int mt = 0; mt < 2; mt++)
#pragma unroll
        for (int j = 0; j < 8; j++) {
            int col = cbase + j * 8;
            int row = rbase + mt * 16;
            *(float2*)(g_dec + (size_t)row * KDIM2 + col) = make_float2(acc[mt][j][0], acc[mt][j][1]);
            *(float2*)(g_dec + (size_t)(row + 8) * KDIM2 + col) = make_float2(acc[mt][j][2], acc[mt][j][3]);
        }
#undef K2_LOAD
}

// ---------------------------------------------------------------------------
// K2b: sigmoid + tree path products.  block = one batch row
// ---------------------------------------------------------------------------
__global__ __launch_bounds__(256) void k2b_prod() {
    const int b   = blockIdx.x;
    const int tid = threadIdx.x;
    __shared__ float s[KDIM2];
    const float* src = g_dec + (size_t)b * KDIM2;
#pragma unroll
    for (int i = 0; i < 10; i++) {
        float z = src[i * 256 + tid];
        s[i * 256 + tid] = 1.f / (1.f + __expf(-z));
    }
    __syncthreads();
    __nv_bfloat16* dst = g_prob + (size_t)b * KDIM2;
    const int m = tid;
#pragma unroll
    for (int t = 0; t < 10; t++) {
        float prod = 1.f;
#pragma unroll
        for (int n = 0; n < 8; n++) {
            int node = (1 << n) - 1 + (m >> (8 - n));
            float p = s[t * 256 + node];
            prod *= ((m >> (7 - n)) & 1) ? (1.f - p) : p;
        }
        dst[t * 256 + m] = __float2bfloat16(prod);
    }
}

// ---------------------------------------------------------------------------
// K3: bf16 mma GEMM  out[128x128] = prob[128x2560] * leafp^T
// grid (8, BATCH/128), 3-stage pipeline, smem 3 x 20480 = 61440
// ---------------------------------------------------------------------------
#define K3_ASZ 10240
#define K3_STG 20480
__global__ __launch_bounds__(256, 1) void k3_mma(float* __restrict__ out) {
    extern __shared__ char smem[];
    const uint32_t sb = smem_u32(smem);
    const int ct   = blockIdx.x;
    const int row0 = blockIdx.y * 128;
    const int tid  = threadIdx.x;
    const int lane = tid & 31, wid = tid >> 5;
    const int wm = wid & 3, wn = wid >> 2;

    const __nv_bfloat16* pA = g_prob + (size_t)row0 * KDIM2;
    const __nv_bfloat16* pB = g_lpb + (size_t)(ct * 128) * KDIM2;

    const int arow = lane & 15, akof = (lane >> 4) * 8;
    const uint32_t aoff0 = ((wm * 32 + arow) * 40 + akof) * 2;
    const uint32_t aoff1 = ((wm * 32 + 16 + arow) * 40 + akof) * 2;
    const int bg = lane >> 3;
    const int brow = ((bg >> 1) * 8) + (lane & 7);
    const int bkof = (bg & 1) * 8;
    uint32_t boff[4];
#pragma unroll
    for (int q = 0; q < 4; q++)
        boff[q] = ((wn * 64 + q * 16 + brow) * 40 + bkof) * 2;

    float acc[2][8][4];
#pragma unroll
    for (int a = 0; a < 2; a++)
#pragma unroll
        for (int b = 0; b < 8; b++)
#pragma unroll
            for (int c = 0; c < 4; c++) acc[a][b][c] = 0.f;

    const int NC = KDIM2 / 32;   // 80

#define K3_LOAD(cc, stg) do {                                                     \
        const uint32_t st_ = sb + (uint32_t)(stg) * K3_STG;                       \
        const int k0_ = (cc) * 32;                                                \
        _Pragma("unroll")                                                         \
        for (int i_ = 0; i_ < 2; i_++) {                                          \
            int idx_ = tid + i_ * 256;                                            \
            int row_ = idx_ >> 2, ch_ = idx_ & 3;                                 \
            uint32_t d_ = st_ + (row_ * 40 + ch_ * 8) * 2;                        \
            CPA(d_,          (const char*)(pA + (size_t)row_ * KDIM2 + k0_ + ch_ * 8)); \
            CPA(d_ + K3_ASZ, (const char*)(pB + (size_t)row_ * KDIM2 + k0_ + ch_ * 8)); \
        }                                                                         \
    } while (0)

    K3_LOAD(0, 0); CPC();
    K3_LOAD(1, 1); CPC();

    int stg = 0;
    for (int c = 0; c < NC; c++) {
        CPW1();
        __syncthreads();
        if (c + 2 < NC) {
            int ps = stg + 2; if (ps >= 3) ps -= 3;
            K3_LOAD(c + 2, ps);
        }
        CPC();
        const uint32_t st = sb + (uint32_t)stg * K3_STG;
#pragma unroll
        for (int ks = 0; ks < 2; ks++) {
            const uint32_t kb = ks * 32;
            uint32_t a[2][4];
            ldsm4(a[0], st + aoff0 + kb);
            ldsm4(a[1], st + aoff1 + kb);
            uint32_t b[4][4];
#pragma unroll
            for (int q = 0; q < 4; q++)
                ldsm4(b[q], st + K3_ASZ + boff[q] + kb);
#pragma unroll
            for (int mt = 0; mt < 2; mt++)
#pragma unroll
                for (int q = 0; q < 4; q++) {
                    mma16816(acc[mt][2 * q],     a[mt], &b[q][0]);
                    mma16816(acc[mt][2 * q + 1], a[mt], &b[q][2]);
                }
        }
        __syncthreads();
        stg++; if (stg == 3) stg = 0;
    }

    const int cbase = ct * 128 + wn * 64 + 2 * (lane & 3);
    const int rbase = row0 + wm * 32 + (lane >> 2);
#pragma unroll
    for (int mt = 0; mt < 2; mt++)
#pragma unroll
        for (int j = 0; j < 8; j++) {
            int col = cbase + j * 8;
            int r0w = rbase + mt * 16;
            if (col + 1 < CLASSES) {
                *(float2*)(out + (size_t)r0w * CLASSES + col) = make_float2(acc[mt][j][0], acc[mt][j][1]);
                *(float2*)(out + (size_t)(r0w + 8) * CLASSES + col) = make_float2(acc[mt][j][2], acc[mt][j][3]);
            } else if (col < CLASSES) {
                out[(size_t)r0w * CLASSES + col] = acc[mt][j][0];
                out[(size_t)(r0w + 8) * CLASSES + col] = acc[mt][j][2];
            }
        }
#undef K3_LOAD
}

// ---------------------------------------------------------------------------
extern "C" void kernel_launch(void* const* d_in, const int* in_sizes, int n_in,
                              void* d_out, int out_size) {
    const float* x = nullptr;
    const float* wd = nullptr;
    const float* wl = nullptr;
    for (int i = 0; i < n_in; i++) {
        if (in_sizes[i] == BATCH * IN_DIM)              x = (const float*)d_in[i];
        else if (in_sizes[i] == NTREES * IN_DIM * NDEC) wd = (const float*)d_in[i];
        else if (in_sizes[i] == NTREES * 512 * CLASSES) wl = (const float*)d_in[i];
    }
    float* out = (float*)d_out;

    cudaFuncSetAttribute(k2_mma, cudaFuncAttributeMaxDynamicSharedMemorySize, 3 * K2_STG);
    cudaFuncSetAttribute(k3_mma, cudaFuncAttributeMaxDynamicSharedMemorySize, 3 * K3_STG);

    p2_wconv<<<dim3(IN_DIM / 32, NTREES), 256>>>(wd);
    k1_softmax<<<NTREES * 256, 256>>>(wl);
    k2_mma<<<dim3(NTREES * 2, BATCH / 128), 256, 3 * K2_STG>>>(x);
    k2b_prod<<<BATCH, 256>>>();
    k3_mma<<<dim3(8, BATCH / 128), 256, 3 * K3_STG>>>(out);
}

// round 5
// speedup vs baseline: 3.9552x; 1.1116x over previous
#include <cuda_runtime.h>
#include <cuda_bf16.h>
#include <cstdint>

#define BATCH   16384
#define IN_DIM  2048
#define NTREES  10
#define NDEC    255
#define CLASSES 1000
#define KDIM2   2560          // NTREES * 256
#define NPAD    1024          // padded class rows for K3 B matrix

// ---------------- device scratch ----------------
__device__ float         g_wt[(size_t)NTREES * 256 * IN_DIM];   // tf32-rounded, [t][n][k]
__device__ __nv_bfloat16 g_lpb[(size_t)NPAD * KDIM2];           // [class][k] K-major
__device__ __nv_bfloat16 g_prob[(size_t)BATCH * KDIM2];

// ---------------- PTX helpers ----------------
__device__ __forceinline__ uint32_t smem_u32(const void* p) {
    uint32_t a;
    asm("{ .reg .u64 t; cvta.to.shared.u64 t, %1; cvt.u32.u64 %0, t; }" : "=r"(a) : "l"(p));
    return a;
}
#define CPA(dst, src) asm volatile("cp.async.cg.shared.global [%0], [%1], 16;" :: "r"(dst), "l"(src))
#define CPC()  asm volatile("cp.async.commit_group;" ::: "memory")
#define CPW1() asm volatile("cp.async.wait_group 1;" ::: "memory")
#define CPW2() asm volatile("cp.async.wait_group 2;" ::: "memory")

__device__ __forceinline__ void ldsm4(uint32_t* r, uint32_t addr) {
    asm volatile("ldmatrix.sync.aligned.m8n8.x4.shared.b16 {%0,%1,%2,%3}, [%4];"
                 : "=r"(r[0]), "=r"(r[1]), "=r"(r[2]), "=r"(r[3]) : "r"(addr));
}
__device__ __forceinline__ void mma16816(float* c, const uint32_t* a, const uint32_t* b) {
    asm volatile("mma.sync.aligned.m16n8k16.row.col.f32.bf16.bf16.f32 "
                 "{%0,%1,%2,%3}, {%4,%5,%6,%7}, {%8,%9}, {%0,%1,%2,%3};"
                 : "+f"(c[0]), "+f"(c[1]), "+f"(c[2]), "+f"(c[3])
                 : "r"(a[0]), "r"(a[1]), "r"(a[2]), "r"(a[3]), "r"(b[0]), "r"(b[1]));
}
__device__ __forceinline__ void mma1688(float* c, const uint32_t* a, const uint32_t* b) {
    asm volatile("mma.sync.aligned.m16n8k8.row.col.f32.tf32.tf32.f32 "
                 "{%0,%1,%2,%3}, {%4,%5,%6,%7}, {%8,%9}, {%0,%1,%2,%3};"
                 : "+f"(c[0]), "+f"(c[1]), "+f"(c[2]), "+f"(c[3])
                 : "r"(a[0]), "r"(a[1]), "r"(a[2]), "r"(a[3]), "r"(b[0]), "r"(b[1]));
}
__device__ __forceinline__ float cvt_tf32(float v) {
    uint32_t r;
    asm("cvt.rna.tf32.f32 %0, %1;" : "=r"(r) : "f"(v));
    return __uint_as_float(r);
}

// ---------------------------------------------------------------------------
// P2: w_d [t][k][255] -> g_wt [t][n(256 pad)][k] fp32 (tf32-rounded), K-major
// ---------------------------------------------------------------------------
__global__ __launch_bounds__(256) void p2_wconv(const float* __restrict__ wd) {
    __shared__ float sh[32][257];
    const int t = blockIdx.y, k0 = blockIdx.x * 32;
    const int n = threadIdx.x;
    const float* wp = wd + (size_t)t * IN_DIM * NDEC;
#pragma unroll
    for (int kk = 0; kk < 32; kk++) {
        float v = (n < NDEC) ? wp[(size_t)(k0 + kk) * NDEC + n] : 0.f;
        sh[kk][n] = cvt_tf32(v);
    }
    __syncthreads();
    float* dst = g_wt + ((size_t)t * 256 + n) * IN_DIM + k0;
#pragma unroll
    for (int u = 0; u < 8; u++) {
        float4 v4;
        v4.x = sh[4 * u + 0][n];
        v4.y = sh[4 * u + 1][n];
        v4.z = sh[4 * u + 2][n];
        v4.w = sh[4 * u + 3][n];
        *(float4*)(dst + 4 * u) = v4;
    }
}

// ---------------------------------------------------------------------------
// K1: paired softmax of w_l -> g_lpb [class][t*256+m] bf16 (K-major for K3)
// ---------------------------------------------------------------------------
__global__ __launch_bounds__(256) void k1_softmax(const float* __restrict__ wl) {
    const int blk = blockIdx.x;
    const int t = blk >> 8, m = blk & 255;
    const int tid = threadIdx.x;
    __shared__ float s[2][CLASSES];
    __shared__ float red[256];

    const float* r0 = wl + (size_t)(t * 512 + 2 * m) * CLASSES;
    for (int i = tid; i < CLASSES; i += 256) { s[0][i] = r0[i]; s[1][i] = r0[CLASSES + i]; }
    __syncthreads();

    float inv[2];
    for (int h = 0; h < 2; h++) {
        float mx = -1e30f;
        for (int i = tid; i < CLASSES; i += 256) mx = fmaxf(mx, s[h][i]);
        red[tid] = mx; __syncthreads();
        for (int o = 128; o > 0; o >>= 1) { if (tid < o) red[tid] = fmaxf(red[tid], red[tid + o]); __syncthreads(); }
        const float M = red[0]; __syncthreads();
        float sm = 0.f;
        for (int i = tid; i < CLASSES; i += 256) { float e = __expf(s[h][i] - M); s[h][i] = e; sm += e; }
        red[tid] = sm; __syncthreads();
        for (int o = 128; o > 0; o >>= 1) { if (tid < o) red[tid] += red[tid + o]; __syncthreads(); }
        inv[h] = 1.f / red[0]; __syncthreads();
    }
    const float sc = 1.f / (float)NTREES;
    for (int i = tid; i < CLASSES; i += 256)
        g_lpb[(size_t)i * KDIM2 + t * 256 + m] =
            __float2bfloat16((s[0][i] * inv[0] + s[1][i] * inv[1]) * sc);
}

// ---------------------------------------------------------------------------
// K2: fused tf32 GEMM (128x256 per tree) + sigmoid + tree products -> g_prob
// grid (NTREES, BATCH/128), 512 threads, 3-stage cp.async pipeline
// smem: 3 x (A[128][36] + B[256][36]) fp32 = 165888 B; epilogue P[128][258]
// ---------------------------------------------------------------------------
#define K2_AB  18432u
#define K2_STG 55296u
__global__ __launch_bounds__(512, 1) void k2_mma(const float* __restrict__ x) {
    extern __shared__ char smem[];
    const uint32_t sb = smem_u32(smem);
    const int t    = blockIdx.x;
    const int row0 = blockIdx.y * 128;
    const int tid  = threadIdx.x;
    const int lane = tid & 31, wid = tid >> 5;
    const int wm = wid & 3, wn = wid >> 2;     // 4 x 4 warps: 32 rows x 64 cols

    const float* pA = x + (size_t)row0 * IN_DIM;
    const float* pB = g_wt + (size_t)t * 256 * IN_DIM;

    // ldmatrix per-lane byte offsets (within a stage's A or B region)
    const int m_off = ((lane >> 3) & 1) * 8 + (lane & 7);
    const int ak    = (lane >> 4) * 4;
    const uint32_t aoff0 = ((wm * 32 + m_off) * 36 + ak) * 4;
    const uint32_t aoff1 = ((wm * 32 + 16 + m_off) * 36 + ak) * 4;
    const int n_off = (lane >> 4) * 8 + (lane & 7);
    const int bk    = ((lane >> 3) & 1) * 4;
    uint32_t boff[4];
#pragma unroll
    for (int q = 0; q < 4; q++)
        boff[q] = ((wn * 64 + q * 16 + n_off) * 36 + bk) * 4;

    float acc[2][8][4];
#pragma unroll
    for (int a = 0; a < 2; a++)
#pragma unroll
        for (int b = 0; b < 8; b++)
#pragma unroll
            for (int c = 0; c < 4; c++) acc[a][b][c] = 0.f;

    const int NC = IN_DIM / 32;   // 64 chunks of k=32

#define K2_LOAD(cc, stg) do {                                                     \
        const uint32_t st_ = sb + (uint32_t)(stg) * K2_STG;                       \
        const int k0_ = (cc) * 32;                                                \
        _Pragma("unroll")                                                         \
        for (int i_ = 0; i_ < 2; i_++) {                                          \
            int idx_ = tid + i_ * 512;                                            \
            int row_ = idx_ >> 3, ch_ = idx_ & 7;                                 \
            uint32_t d_ = st_ + (row_ * 36 + ch_ * 4) * 4;                        \
            CPA(d_, (const char*)(pA + (size_t)row_ * IN_DIM + k0_ + ch_ * 4));   \
        }                                                                         \
        _Pragma("unroll")                                                         \
        for (int i_ = 0; i_ < 4; i_++) {                                          \
            int idx_ = tid + i_ * 512;                                            \
            int row_ = idx_ >> 3, ch_ = idx_ & 7;                                 \
            uint32_t d_ = st_ + K2_AB + (row_ * 36 + ch_ * 4) * 4;                \
            CPA(d_, (const char*)(pB + (size_t)row_ * IN_DIM + k0_ + ch_ * 4));   \
        }                                                                         \
    } while (0)

    K2_LOAD(0, 0); CPC();
    K2_LOAD(1, 1); CPC();

    int stg = 0;
    for (int c = 0; c < NC; c++) {
        CPW1();
        __syncthreads();
        if (c + 2 < NC) {
            int ps = stg + 2; if (ps >= 3) ps -= 3;
            K2_LOAD(c + 2, ps);
        }
        CPC();
        const uint32_t st = sb + (uint32_t)stg * K2_STG;
#pragma unroll
        for (int ks = 0; ks < 4; ks++) {
            const uint32_t kb = ks * 32;      // 8 floats
            uint32_t a[2][4];
            ldsm4(a[0], st + aoff0 + kb);
            ldsm4(a[1], st + aoff1 + kb);
#pragma unroll
            for (int q = 0; q < 4; q++) {
                uint32_t b[4];
                ldsm4(b, st + K2_AB + boff[q] + kb);
                mma1688(acc[0][2 * q],     a[0], b + 0);
                mma1688(acc[0][2 * q + 1], a[0], b + 2);
                mma1688(acc[1][2 * q],     a[1], b + 0);
                mma1688(acc[1][2 * q + 1], a[1], b + 2);
            }
        }
        __syncthreads();
        stg++; if (stg == 3) stg = 0;
    }

    // ---------- fused epilogue: sigmoid -> P[128][258], tree products --------
    float* P = (float*)smem;
    const int cbase = wn * 64 + 2 * (lane & 3);
    const int rbase = wm * 32 + (lane >> 2);
#pragma unroll
    for (int mt = 0; mt < 2; mt++)
#pragma unroll
        for (int j = 0; j < 8; j++) {
            const int col = cbase + j * 8;
            const int row = rbase + mt * 16;
            P[row * 258 + col]           = 1.f / (1.f + __expf(-acc[mt][j][0]));
            P[row * 258 + col + 1]       = 1.f / (1.f + __expf(-acc[mt][j][1]));
            P[(row + 8) * 258 + col]     = 1.f / (1.f + __expf(-acc[mt][j][2]));
            P[(row + 8) * 258 + col + 1] = 1.f / (1.f + __expf(-acc[mt][j][3]));
        }
    __syncthreads();

    const int m  = tid & 255;
    const int rh = tid >> 8;       // 0 or 1: rows [rh*64, rh*64+64)
    __nv_bfloat16* dst = g_prob + (size_t)(row0 + rh * 64) * KDIM2 + t * 256 + m;
    for (int r = 0; r < 64; r++) {
        const float* Pr = P + (rh * 64 + r) * 258;
        float prod = 1.f;
#pragma unroll
        for (int n = 0; n < 8; n++) {
            int node = (1 << n) - 1 + (m >> (8 - n));
            float p = Pr[node];
            prod *= ((m >> (7 - n)) & 1) ? (1.f - p) : p;
        }
        dst[(size_t)r * KDIM2] = __float2bfloat16(prod);
    }
#undef K2_LOAD
}

// ---------------------------------------------------------------------------
// K3: bf16 mma GEMM  out[128x128] = prob[128x2560] * leafp^T
// grid (8, BATCH/128), 4-stage pipeline, smem 4 x 20480 = 81920
// ---------------------------------------------------------------------------
#define K3_ASZ 10240
#define K3_STG 20480
__global__ __launch_bounds__(256, 1) void k3_mma(float* __restrict__ out) {
    extern __shared__ char smem[];
    const uint32_t sb = smem_u32(smem);
    const int ct   = blockIdx.x;
    const int row0 = blockIdx.y * 128;
    const int tid  = threadIdx.x;
    const int lane = tid & 31, wid = tid >> 5;
    const int wm = wid & 3, wn = wid >> 2;

    const __nv_bfloat16* pA = g_prob + (size_t)row0 * KDIM2;
    const __nv_bfloat16* pB = g_lpb + (size_t)(ct * 128) * KDIM2;

    const int arow = lane & 15, akof = (lane >> 4) * 8;
    const uint32_t aoff0 = ((wm * 32 + arow) * 40 + akof) * 2;
    const uint32_t aoff1 = ((wm * 32 + 16 + arow) * 40 + akof) * 2;
    const int bg = lane >> 3;
    const int brow = ((bg >> 1) * 8) + (lane & 7);
    const int bkof = (bg & 1) * 8;
    uint32_t boff[4];
#pragma unroll
    for (int q = 0; q < 4; q++)
        boff[q] = ((wn * 64 + q * 16 + brow) * 40 + bkof) * 2;

    float acc[2][8][4];
#pragma unroll
    for (int a = 0; a < 2; a++)
#pragma unroll
        for (int b = 0; b < 8; b++)
#pragma unroll
            for (int c = 0; c < 4; c++) acc[a][b][c] = 0.f;

    const int NC = KDIM2 / 32;   // 80

#define K3_LOAD(cc, stg) do {                                                     \
        const uint32_t st_ = sb + (uint32_t)(stg) * K3_STG;                       \
        const int k0_ = (cc) * 32;                                                \
        _Pragma("unroll")                                                         \
        for (int i_ = 0; i_ < 2; i_++) {                                          \
            int idx_ = tid + i_ * 256;                                            \
            int row_ = idx_ >> 2, ch_ = idx_ & 3;                                 \
            uint32_t d_ = st_ + (row_ * 40 + ch_ * 8) * 2;                        \
            CPA(d_,          (const char*)(pA + (size_t)row_ * KDIM2 + k0_ + ch_ * 8)); \
            CPA(d_ + K3_ASZ, (const char*)(pB + (size_t)row_ * KDIM2 + k0_ + ch_ * 8)); \
        }                                                                         \
    } while (0)

    K3_LOAD(0, 0); CPC();
    K3_LOAD(1, 1); CPC();
    K3_LOAD(2, 2); CPC();

    int stg = 0;
    for (int c = 0; c < NC; c++) {
        CPW2();
        __syncthreads();
        if (c + 3 < NC) {
            int ps = stg + 3; if (ps >= 4) ps -= 4;
            K3_LOAD(c + 3, ps);
        }
        CPC();
        const uint32_t st = sb + (uint32_t)stg * K3_STG;
#pragma unroll
        for (int ks = 0; ks < 2; ks++) {
            const uint32_t kb = ks * 32;
            uint32_t a[2][4];
            ldsm4(a[0], st + aoff0 + kb);
            ldsm4(a[1], st + aoff1 + kb);
            uint32_t b[4][4];
#pragma unroll
            for (int q = 0; q < 4; q++)
                ldsm4(b[q], st + K3_ASZ + boff[q] + kb);
#pragma unroll
            for (int mt = 0; mt < 2; mt++)
#pragma unroll
                for (int q = 0; q < 4; q++) {
                    mma16816(acc[mt][2 * q],     a[mt], &b[q][0]);
                    mma16816(acc[mt][2 * q + 1], a[mt], &b[q][2]);
                }
        }
        __syncthreads();
        stg++; if (stg == 4) stg = 0;
    }

    const int cbase = ct * 128 + wn * 64 + 2 * (lane & 3);
    const int rbase = row0 + wm * 32 + (lane >> 2);
#pragma unroll
    for (int mt = 0; mt < 2; mt++)
#pragma unroll
        for (int j = 0; j < 8; j++) {
            int col = cbase + j * 8;
            int r0w = rbase + mt * 16;
            if (col + 1 < CLASSES) {
                *(float2*)(out + (size_t)r0w * CLASSES + col) = make_float2(acc[mt][j][0], acc[mt][j][1]);
                *(float2*)(out + (size_t)(r0w + 8) * CLASSES + col) = make_float2(acc[mt][j][2], acc[mt][j][3]);
            } else if (col < CLASSES) {
                out[(size_t)r0w * CLASSES + col] = acc[mt][j][0];
                out[(size_t)(r0w + 8) * CLASSES + col] = acc[mt][j][2];
            }
        }
#undef K3_LOAD
}

// ---------------------------------------------------------------------------
extern "C" void kernel_launch(void* const* d_in, const int* in_sizes, int n_in,
                              void* d_out, int out_size) {
    const float* x = nullptr;
    const float* wd = nullptr;
    const float* wl = nullptr;
    for (int i = 0; i < n_in; i++) {
        if (in_sizes[i] == BATCH * IN_DIM)              x = (const float*)d_in[i];
        else if (in_sizes[i] == NTREES * IN_DIM * NDEC) wd = (const float*)d_in[i];
        else if (in_sizes[i] == NTREES * 512 * CLASSES) wl = (const float*)d_in[i];
    }
    float* out = (float*)d_out;

    cudaFuncSetAttribute(k2_mma, cudaFuncAttributeMaxDynamicSharedMemorySize, 3 * K2_STG);
    cudaFuncSetAttribute(k3_mma, cudaFuncAttributeMaxDynamicSharedMemorySize, 4 * K3_STG);

    p2_wconv<<<dim3(IN_DIM / 32, NTREES), 256>>>(wd);
    k1_softmax<<<NTREES * 256, 256>>>(wl);
    k2_mma<<<dim3(NTREES, BATCH / 128), 512, 3 * K2_STG>>>(x);
    k3_mma<<<dim3(8, BATCH / 128), 256, 4 * K3_STG>>>(out);
}

// round 6
// speedup vs baseline: 6.0562x; 1.5312x over previous
#include <cuda_runtime.h>
#include <cuda_bf16.h>
#include <cuda_fp16.h>
#include <cstdint>

#define BATCH   16384
#define IN_DIM  2048
#define NTREES  10
#define NDEC    255
#define CLASSES 1000
#define KDIM2   2560          // NTREES * 256
#define NPAD    1024          // padded class rows for K3 B matrix

// ---------------- device scratch ----------------
__device__ __half         g_xf[(size_t)BATCH * IN_DIM];          // x in fp16
__device__ __half         g_wf[(size_t)NTREES * 256 * IN_DIM];   // w fp16, [t][n][k]
__device__ __nv_bfloat16  g_lpb[(size_t)NPAD * KDIM2];           // [class][k] K-major
__device__ __nv_bfloat16  g_prob[(size_t)BATCH * KDIM2];

// ---------------- PTX helpers ----------------
__device__ __forceinline__ uint32_t smem_u32(const void* p) {
    uint32_t a;
    asm("{ .reg .u64 t; cvta.to.shared.u64 t, %1; cvt.u32.u64 %0, t; }" : "=r"(a) : "l"(p));
    return a;
}
#define CPA(dst, src) asm volatile("cp.async.cg.shared.global [%0], [%1], 16;" :: "r"(dst), "l"(src))
#define CPC()  asm volatile("cp.async.commit_group;" ::: "memory")
#define CPW1() asm volatile("cp.async.wait_group 1;" ::: "memory")
#define CPW2() asm volatile("cp.async.wait_group 2;" ::: "memory")

__device__ __forceinline__ void ldsm4(uint32_t* r, uint32_t addr) {
    asm volatile("ldmatrix.sync.aligned.m8n8.x4.shared.b16 {%0,%1,%2,%3}, [%4];"
                 : "=r"(r[0]), "=r"(r[1]), "=r"(r[2]), "=r"(r[3]) : "r"(addr));
}
__device__ __forceinline__ void mma_bf16(float* c, const uint32_t* a, const uint32_t* b) {
    asm volatile("mma.sync.aligned.m16n8k16.row.col.f32.bf16.bf16.f32 "
                 "{%0,%1,%2,%3}, {%4,%5,%6,%7}, {%8,%9}, {%0,%1,%2,%3};"
                 : "+f"(c[0]), "+f"(c[1]), "+f"(c[2]), "+f"(c[3])
                 : "r"(a[0]), "r"(a[1]), "r"(a[2]), "r"(a[3]), "r"(b[0]), "r"(b[1]));
}
__device__ __forceinline__ void mma_f16(float* c, const uint32_t* a, const uint32_t* b) {
    asm volatile("mma.sync.aligned.m16n8k16.row.col.f32.f16.f16.f32 "
                 "{%0,%1,%2,%3}, {%4,%5,%6,%7}, {%8,%9}, {%0,%1,%2,%3};"
                 : "+f"(c[0]), "+f"(c[1]), "+f"(c[2]), "+f"(c[3])
                 : "r"(a[0]), "r"(a[1]), "r"(a[2]), "r"(a[3]), "r"(b[0]), "r"(b[1]));
}

// ---------------------------------------------------------------------------
// P1: x fp32 -> fp16   (8 elements / thread)
// ---------------------------------------------------------------------------
__global__ __launch_bounds__(256) void p1_xconv(const float* __restrict__ x) {
    size_t i = ((size_t)blockIdx.x * 256 + threadIdx.x) * 8;
    float4 v0 = *(const float4*)(x + i);
    float4 v1 = *(const float4*)(x + i + 4);
    __half2 h0 = __floats2half2_rn(v0.x, v0.y);
    __half2 h1 = __floats2half2_rn(v0.z, v0.w);
    __half2 h2 = __floats2half2_rn(v1.x, v1.y);
    __half2 h3 = __floats2half2_rn(v1.z, v1.w);
    uint4 u{*(uint32_t*)&h0, *(uint32_t*)&h1, *(uint32_t*)&h2, *(uint32_t*)&h3};
    *(uint4*)(g_xf + i) = u;
}

// ---------------------------------------------------------------------------
// P2: w_d [t][k][255] -> g_wf [t][n(256 pad)][k] fp16, K-major
// ---------------------------------------------------------------------------
__global__ __launch_bounds__(256) void p2_wconv(const float* __restrict__ wd) {
    __shared__ float sh[32][257];
    const int t = blockIdx.y, k0 = blockIdx.x * 32;
    const int n = threadIdx.x;
    const float* wp = wd + (size_t)t * IN_DIM * NDEC;
#pragma unroll
    for (int kk = 0; kk < 32; kk++)
        sh[kk][n] = (n < NDEC) ? wp[(size_t)(k0 + kk) * NDEC + n] : 0.f;
    __syncthreads();
    __half* dst = g_wf + ((size_t)t * 256 + n) * IN_DIM + k0;
#pragma unroll
    for (int u = 0; u < 4; u++) {
        __half2 p0 = __floats2half2_rn(sh[8 * u + 0][n], sh[8 * u + 1][n]);
        __half2 p1 = __floats2half2_rn(sh[8 * u + 2][n], sh[8 * u + 3][n]);
        __half2 p2 = __floats2half2_rn(sh[8 * u + 4][n], sh[8 * u + 5][n]);
        __half2 p3 = __floats2half2_rn(sh[8 * u + 6][n], sh[8 * u + 7][n]);
        uint4 v{*(uint32_t*)&p0, *(uint32_t*)&p1, *(uint32_t*)&p2, *(uint32_t*)&p3};
        *(uint4*)(dst + 8 * u) = v;
    }
}

// ---------------------------------------------------------------------------
// K1: paired softmax of w_l -> g_lpb [class][t*256+m] bf16 (K-major for K3)
// ---------------------------------------------------------------------------
__global__ __launch_bounds__(256) void k1_softmax(const float* __restrict__ wl) {
    const int blk = blockIdx.x;
    const int t = blk >> 8, m = blk & 255;
    const int tid = threadIdx.x;
    __shared__ float s[2][CLASSES];
    __shared__ float red[256];

    const float* r0 = wl + (size_t)(t * 512 + 2 * m) * CLASSES;
    for (int i = tid; i < CLASSES; i += 256) { s[0][i] = r0[i]; s[1][i] = r0[CLASSES + i]; }
    __syncthreads();

    float inv[2];
    for (int h = 0; h < 2; h++) {
        float mx = -1e30f;
        for (int i = tid; i < CLASSES; i += 256) mx = fmaxf(mx, s[h][i]);
        red[tid] = mx; __syncthreads();
        for (int o = 128; o > 0; o >>= 1) { if (tid < o) red[tid] = fmaxf(red[tid], red[tid + o]); __syncthreads(); }
        const float M = red[0]; __syncthreads();
        float sm = 0.f;
        for (int i = tid; i < CLASSES; i += 256) { float e = __expf(s[h][i] - M); s[h][i] = e; sm += e; }
        red[tid] = sm; __syncthreads();
        for (int o = 128; o > 0; o >>= 1) { if (tid < o) red[tid] += red[tid + o]; __syncthreads(); }
        inv[h] = 1.f / red[0]; __syncthreads();
    }
    const float sc = 1.f / (float)NTREES;
    for (int i = tid; i < CLASSES; i += 256)
        g_lpb[(size_t)i * KDIM2 + t * 256 + m] =
            __float2bfloat16((s[0][i] * inv[0] + s[1][i] * inv[1]) * sc);
}

// ---------------------------------------------------------------------------
// K2: fused fp16 GEMM (128x256 per tree, k=64 chunks) + sigmoid + products
// grid (NTREES, BATCH/128), 512 threads, 3-stage cp.async pipeline
// stage = A[128][72] + B[256][72] fp16 = 55296 B; x3 = 165888
// ---------------------------------------------------------------------------
#define K2_AB  18432u
#define K2_STG 55296u
__global__ __launch_bounds__(512, 1) void k2_mma() {
    extern __shared__ char smem[];
    const uint32_t sb = smem_u32(smem);
    const int t    = blockIdx.x;
    const int row0 = blockIdx.y * 128;
    const int tid  = threadIdx.x;
    const int lane = tid & 31, wid = tid >> 5;
    const int wm = wid & 3, wn = wid >> 2;     // 4 x 4 warps: 32 rows x 64 cols

    const __half* pA = g_xf + (size_t)row0 * IN_DIM;
    const __half* pB = g_wf + (size_t)t * 256 * IN_DIM;

    // ldmatrix per-lane byte offsets (stride 72 halves = 144 B)
    const int arow = lane & 15, akof = (lane >> 4) * 8;
    const uint32_t aoff0 = ((wm * 32 + arow) * 72 + akof) * 2;
    const uint32_t aoff1 = ((wm * 32 + 16 + arow) * 72 + akof) * 2;
    const int bg = lane >> 3;
    const int brow = ((bg >> 1) * 8) + (lane & 7);
    const int bkof = (bg & 1) * 8;
    uint32_t boff[4];
#pragma unroll
    for (int q = 0; q < 4; q++)
        boff[q] = ((wn * 64 + q * 16 + brow) * 72 + bkof) * 2;

    float acc[2][8][4];
#pragma unroll
    for (int a = 0; a < 2; a++)
#pragma unroll
        for (int b = 0; b < 8; b++)
#pragma unroll
            for (int c = 0; c < 4; c++) acc[a][b][c] = 0.f;

    const int NC = IN_DIM / 64;   // 32 chunks of k=64

#define K2_LOAD(cc, stg) do {                                                     \
        const uint32_t st_ = sb + (uint32_t)(stg) * K2_STG;                       \
        const int k0_ = (cc) * 64;                                                \
        _Pragma("unroll")                                                         \
        for (int i_ = 0; i_ < 2; i_++) {                                          \
            int idx_ = tid + i_ * 512;                                            \
            int row_ = idx_ >> 3, ch_ = idx_ & 7;                                 \
            uint32_t d_ = st_ + row_ * 144 + ch_ * 16;                            \
            CPA(d_, (const char*)(pA + (size_t)row_ * IN_DIM + k0_ + ch_ * 8));   \
        }                                                                         \
        _Pragma("unroll")                                                         \
        for (int i_ = 0; i_ < 4; i_++) {                                          \
            int idx_ = tid + i_ * 512;                                            \
            int row_ = idx_ >> 3, ch_ = idx_ & 7;                                 \
            uint32_t d_ = st_ + K2_AB + row_ * 144 + ch_ * 16;                    \
            CPA(d_, (const char*)(pB + (size_t)row_ * IN_DIM + k0_ + ch_ * 8));   \
        }                                                                         \
    } while (0)

    K2_LOAD(0, 0); CPC();
    K2_LOAD(1, 1); CPC();

    int stg = 0;
    for (int c = 0; c < NC; c++) {
        CPW1();
        __syncthreads();
        if (c + 2 < NC) {
            int ps = stg + 2; if (ps >= 3) ps -= 3;
            K2_LOAD(c + 2, ps);
        }
        CPC();
        const uint32_t st = sb + (uint32_t)stg * K2_STG;
#pragma unroll
        for (int ks = 0; ks < 4; ks++) {
            const uint32_t kb = ks * 32;      // 16 halves
            uint32_t a[2][4];
            ldsm4(a[0], st + aoff0 + kb);
            ldsm4(a[1], st + aoff1 + kb);
#pragma unroll
            for (int q = 0; q < 4; q++) {
                uint32_t b[4];
                ldsm4(b, st + K2_AB + boff[q] + kb);
                mma_f16(acc[0][2 * q],     a[0], b + 0);
                mma_f16(acc[0][2 * q + 1], a[0], b + 2);
                mma_f16(acc[1][2 * q],     a[1], b + 0);
                mma_f16(acc[1][2 * q + 1], a[1], b + 2);
            }
        }
        __syncthreads();
        stg++; if (stg == 3) stg = 0;
    }

    // ---------- fused epilogue: sigmoid -> P[128][258], tree products --------
    float* P = (float*)smem;
    const int cbase = wn * 64 + 2 * (lane & 3);
    const int rbase = wm * 32 + (lane >> 2);
#pragma unroll
    for (int mt = 0; mt < 2; mt++)
#pragma unroll
        for (int j = 0; j < 8; j++) {
            const int col = cbase + j * 8;
            const int row = rbase + mt * 16;
            P[row * 258 + col]           = 1.f / (1.f + __expf(-acc[mt][j][0]));
            P[row * 258 + col + 1]       = 1.f / (1.f + __expf(-acc[mt][j][1]));
            P[(row + 8) * 258 + col]     = 1.f / (1.f + __expf(-acc[mt][j][2]));
            P[(row + 8) * 258 + col + 1] = 1.f / (1.f + __expf(-acc[mt][j][3]));
        }
    __syncthreads();

    const int m  = tid & 255;
    const int rh = tid >> 8;       // 0 or 1: rows [rh*64, rh*64+64)
    __nv_bfloat16* dst = g_prob + (size_t)(row0 + rh * 64) * KDIM2 + t * 256 + m;
    for (int r = 0; r < 64; r++) {
        const float* Pr = P + (rh * 64 + r) * 258;
        float prod = 1.f;
#pragma unroll
        for (int n = 0; n < 8; n++) {
            int node = (1 << n) - 1 + (m >> (8 - n));
            float p = Pr[node];
            prod *= ((m >> (7 - n)) & 1) ? (1.f - p) : p;
        }
        dst[(size_t)r * KDIM2] = __float2bfloat16(prod);
    }
#undef K2_LOAD
}

// ---------------------------------------------------------------------------
// K3: bf16 mma GEMM  out[128x128] = prob[128x2560] * leafp^T  (k=64 chunks)
// grid (8, BATCH/128), 4-stage pipeline, stage = 2 x 128x72 bf16 = 36864
// ---------------------------------------------------------------------------
#define K3_ASZ 18432u
#define K3_STG 36864u
__global__ __launch_bounds__(256, 1) void k3_mma(float* __restrict__ out) {
    extern __shared__ char smem[];
    const uint32_t sb = smem_u32(smem);
    const int ct   = blockIdx.x;
    const int row0 = blockIdx.y * 128;
    const int tid  = threadIdx.x;
    const int lane = tid & 31, wid = tid >> 5;
    const int wm = wid & 3, wn = wid >> 2;

    const __nv_bfloat16* pA = g_prob + (size_t)row0 * KDIM2;
    const __nv_bfloat16* pB = g_lpb + (size_t)(ct * 128) * KDIM2;

    const int arow = lane & 15, akof = (lane >> 4) * 8;
    const uint32_t aoff0 = ((wm * 32 + arow) * 72 + akof) * 2;
    const uint32_t aoff1 = ((wm * 32 + 16 + arow) * 72 + akof) * 2;
    const int bg = lane >> 3;
    const int brow = ((bg >> 1) * 8) + (lane & 7);
    const int bkof = (bg & 1) * 8;
    uint32_t boff[4];
#pragma unroll
    for (int q = 0; q < 4; q++)
        boff[q] = ((wn * 64 + q * 16 + brow) * 72 + bkof) * 2;

    float acc[2][8][4];
#pragma unroll
    for (int a = 0; a < 2; a++)
#pragma unroll
        for (int b = 0; b < 8; b++)
#pragma unroll
            for (int c = 0; c < 4; c++) acc[a][b][c] = 0.f;

    const int NC = KDIM2 / 64;   // 40

#define K3_LOAD(cc, stg) do {                                                     \
        const uint32_t st_ = sb + (uint32_t)(stg) * K3_STG;                       \
        const int k0_ = (cc) * 64;                                                \
        _Pragma("unroll")                                                         \
        for (int i_ = 0; i_ < 4; i_++) {                                          \
            int idx_ = tid + i_ * 256;                                            \
            int row_ = idx_ >> 3, ch_ = idx_ & 7;                                 \
            uint32_t d_ = st_ + row_ * 144 + ch_ * 16;                            \
            CPA(d_,          (const char*)(pA + (size_t)row_ * KDIM2 + k0_ + ch_ * 8)); \
            CPA(d_ + K3_ASZ, (const char*)(pB + (size_t)row_ * KDIM2 + k0_ + ch_ * 8)); \
        }                                                                         \
    } while (0)

    K3_LOAD(0, 0); CPC();
    K3_LOAD(1, 1); CPC();
    K3_LOAD(2, 2); CPC();

    int stg = 0;
    for (int c = 0; c < NC; c++) {
        CPW2();
        __syncthreads();
        if (c + 3 < NC) {
            int ps = stg + 3; if (ps >= 4) ps -= 4;
            K3_LOAD(c + 3, ps);
        }
        CPC();
        const uint32_t st = sb + (uint32_t)stg * K3_STG;
#pragma unroll
        for (int ks = 0; ks < 4; ks++) {
            const uint32_t kb = ks * 32;
            uint32_t a[2][4];
            ldsm4(a[0], st + aoff0 + kb);
            ldsm4(a[1], st + aoff1 + kb);
#pragma unroll
            for (int q = 0; q < 4; q++) {
                uint32_t b[4];
                ldsm4(b, st + K3_ASZ + boff[q] + kb);
                mma_bf16(acc[0][2 * q],     a[0], b + 0);
                mma_bf16(acc[0][2 * q + 1], a[0], b + 2);
                mma_bf16(acc[1][2 * q],     a[1], b + 0);
                mma_bf16(acc[1][2 * q + 1], a[1], b + 2);
            }
        }
        __syncthreads();
        stg++; if (stg == 4) stg = 0;
    }

    const int cbase = ct * 128 + wn * 64 + 2 * (lane & 3);
    const int rbase = row0 + wm * 32 + (lane >> 2);
#pragma unroll
    for (int mt = 0; mt < 2; mt++)
#pragma unroll
        for (int j = 0; j < 8; j++) {
            int col = cbase + j * 8;
            int r0w = rbase + mt * 16;
            if (col + 1 < CLASSES) {
                *(float2*)(out + (size_t)r0w * CLASSES + col) = make_float2(acc[mt][j][0], acc[mt][j][1]);
                *(float2*)(out + (size_t)(r0w + 8) * CLASSES + col) = make_float2(acc[mt][j][2], acc[mt][j][3]);
            } else if (col < CLASSES) {
                out[(size_t)r0w * CLASSES + col] = acc[mt][j][0];
                out[(size_t)(r0w + 8) * CLASSES + col] = acc[mt][j][2];
            }
        }
#undef K3_LOAD
}

// ---------------------------------------------------------------------------
extern "C" void kernel_launch(void* const* d_in, const int* in_sizes, int n_in,
                              void* d_out, int out_size) {
    const float* x = nullptr;
    const float* wd = nullptr;
    const float* wl = nullptr;
    for (int i = 0; i < n_in; i++) {
        if (in_sizes[i] == BATCH * IN_DIM)              x = (const float*)d_in[i];
        else if (in_sizes[i] == NTREES * IN_DIM * NDEC) wd = (const float*)d_in[i];
        else if (in_sizes[i] == NTREES * 512 * CLASSES) wl = (const float*)d_in[i];
    }
    float* out = (float*)d_out;

    cudaFuncSetAttribute(k2_mma, cudaFuncAttributeMaxDynamicSharedMemorySize, 3 * K2_STG);
    cudaFuncSetAttribute(k3_mma, cudaFuncAttributeMaxDynamicSharedMemorySize, 4 * K3_STG);

    p1_xconv<<<BATCH * IN_DIM / 8 / 256, 256>>>(x);
    p2_wconv<<<dim3(IN_DIM / 32, NTREES), 256>>>(wd);
    k1_softmax<<<NTREES * 256, 256>>>(wl);
    k2_mma<<<dim3(NTREES, BATCH / 128), 512, 3 * K2_STG>>>();
    k3_mma<<<dim3(8, BATCH / 128), 256, 4 * K3_STG>>>(out);
}